// round 15
// baseline (speedup 1.0000x reference)
#include <cuda_runtime.h>
#include <cuda_fp16.h>
#include <math.h>

#define N_NODES 50000
#define IN_F    256
#define OUT_F   64
#define N_EDGES 1600000
#define ALPHA   0.2f

#define SCAN_BLOCKS 196   // 196*256 = 50176 >= 50000

// gemm tiling: 64 nodes x 64 f per block, 256 threads, 2n x 8f per thread
#define GB_NODES 64
#define GB_THREADS 256
#define KCHUNK 64
#define XS_ROW 65
#define WT_ROW 48

typedef unsigned long long ull;

// ---------------- scratch (static device globals; no allocation) ----------------
__device__ __align__(16) __half g_hh[(size_t)N_NODES * OUT_F]; // 6.4 MB (fp16 h)
__device__ float g_s1[N_NODES];
__device__ float g_s2[N_NODES];
__device__ int   g_count[N_NODES];
__device__ int   g_rowstart[N_NODES + 1];
__device__ int   g_blocksum[SCAN_BLOCKS];
__device__ __align__(16) int g_rank[N_EDGES];                  // 6.4 MB
__device__ __align__(16) ull g_csr[N_EDGES];                   // 12.8 MB packed (dst, w)

// ---------------- zero histogram ----------------
__global__ void k_init() {
    int idx = blockIdx.x * blockDim.x + threadIdx.x;
    if (idx < N_NODES) g_count[idx] = 0;
}

// ---------------- histogram of src + per-edge rank ----------------
__global__ __launch_bounds__(256) void k_hist_rank(const int* __restrict__ ei) {
    int t = blockIdx.x * blockDim.x + threadIdx.x;
    if (t >= N_EDGES / 4) return;
    int4 v = ((const int4*)ei)[t];
    int4 r;
    r.x = atomicAdd(&g_count[v.x], 1);
    r.y = atomicAdd(&g_count[v.y], 1);
    r.z = atomicAdd(&g_count[v.z], 1);
    r.w = atomicAdd(&g_count[v.w], 1);
    ((int4*)g_rank)[t] = r;
}

// ---------------- scan stage A: per-block sums ----------------
__global__ __launch_bounds__(256) void k_scan_a() {
    __shared__ int sh[256];
    int i = blockIdx.x * 256 + threadIdx.x;
    sh[threadIdx.x] = (i < N_NODES) ? g_count[i] : 0;
    __syncthreads();
    for (int o = 128; o > 0; o >>= 1) {
        if (threadIdx.x < o) sh[threadIdx.x] += sh[threadIdx.x + o];
        __syncthreads();
    }
    if (threadIdx.x == 0) g_blocksum[blockIdx.x] = sh[0];
}

// ---------------- scan stage C2: self-service global offset + local scan ----------
__global__ __launch_bounds__(256) void k_scan_c2() {
    __shared__ int sh[256];
    __shared__ int s_base;
    int t = threadIdx.x;

    int partial = 0;
    if (t < SCAN_BLOCKS && t < blockIdx.x) partial = g_blocksum[t];
    sh[t] = partial;
    __syncthreads();
    for (int o = 128; o > 0; o >>= 1) {
        if (t < o) sh[t] += sh[t + o];
        __syncthreads();
    }
    if (t == 0) s_base = sh[0];
    __syncthreads();

    int i = blockIdx.x * 256 + t;
    int cnt = (i < N_NODES) ? g_count[i] : 0;
    sh[t] = cnt;
    __syncthreads();
    #pragma unroll
    for (int o = 1; o < 256; o <<= 1) {
        int v = 0;
        if (t >= o) v = sh[t - o];
        __syncthreads();
        sh[t] += v;
        __syncthreads();
    }
    if (i < N_NODES) g_rowstart[i] = s_base + sh[t] - cnt;
    if (blockIdx.x == SCAN_BLOCKS - 1 && t == 0) g_rowstart[N_NODES] = N_EDGES;
}

// ---------------- h = x @ W (fp16 store) + fused scores s1/s2 ----------------
// 256 threads: tx = tid&7 -> f0 = tx*8; ty = tid>>3 -> nodes n0 = ty*2 (2 per thread)
__global__ __launch_bounds__(GB_THREADS, 4) void k_gemm(const float* __restrict__ x,
                                                        const float* __restrict__ W,
                                                        const float* __restrict__ a) {
    __shared__ float xs[GB_NODES * XS_ROW];            // 16.6 KB
    __shared__ __align__(16) ull Wt[KCHUNK * WT_ROW];  // 24.6 KB

    const int tid = threadIdx.x;
    const int tx = tid & 7;
    const int ty = tid >> 3;
    const int f0 = tx * 8;
    const int n0 = ty * 2;
    const int nodeBase = blockIdx.x * GB_NODES;

    ull acc[2][4];
    #pragma unroll
    for (int j = 0; j < 2; j++)
        #pragma unroll
        for (int p = 0; p < 4; p++) acc[j][p] = 0ull;

    for (int kc = 0; kc < IN_F; kc += KCHUNK) {
        __syncthreads();
        // stage x chunk: 64 nodes x 64 k (4 float4 per thread, coalesced)
        #pragma unroll
        for (int i = 0; i < (GB_NODES * KCHUNK / 4) / GB_THREADS; i++) {
            int flat = i * GB_THREADS + tid;      // [0, 1024)
            int node = flat >> 4;
            int kv   = flat & 15;
            int gn   = nodeBase + node;
            float4 v = make_float4(0.f, 0.f, 0.f, 0.f);
            if (gn < N_NODES)
                v = *(const float4*)(x + (size_t)gn * IN_F + kc + kv * 4);
            float* dst = &xs[node * XS_ROW + kv * 4];
            dst[0] = v.x; dst[1] = v.y; dst[2] = v.z; dst[3] = v.w;
        }
        // stage W chunk: 64 k x 64 f (4 float4 per thread, coalesced, padded groups)
        #pragma unroll
        for (int i = 0; i < (KCHUNK * OUT_F / 4) / GB_THREADS; i++) {
            int flat = i * GB_THREADS + tid;      // [0, 1024)
            int kr = flat >> 4;
            int kv = flat & 15;
            float4 v = *(const float4*)(W + (size_t)(kc + kr) * OUT_F + kv * 4);
            *(ulonglong2*)&Wt[kr * WT_ROW + (kv >> 1) * 6 + (kv & 1) * 2] =
                *(ulonglong2*)&v;
        }
        __syncthreads();

        #pragma unroll 4
        for (int k = 0; k < KCHUNK; k++) {
            const ull* wrow = &Wt[k * WT_ROW + tx * 6];
            ull w0 = wrow[0], w1 = wrow[1], w2 = wrow[2], w3 = wrow[3];
            const float* xcol = &xs[n0 * XS_ROW + k];
            #pragma unroll
            for (int j = 0; j < 2; j++) {
                float xv = xcol[j * XS_ROW];
                ull xp;
                asm("mov.b64 %0, {%1, %1};" : "=l"(xp) : "r"(__float_as_uint(xv)));
                asm("fma.rn.f32x2 %0, %1, %2, %0;" : "+l"(acc[j][0]) : "l"(xp), "l"(w0));
                asm("fma.rn.f32x2 %0, %1, %2, %0;" : "+l"(acc[j][1]) : "l"(xp), "l"(w1));
                asm("fma.rn.f32x2 %0, %1, %2, %0;" : "+l"(acc[j][2]) : "l"(xp), "l"(w2));
                asm("fma.rn.f32x2 %0, %1, %2, %0;" : "+l"(acc[j][3]) : "l"(xp), "l"(w3));
            }
        }
    }

    // epilogue: fp16 h store + fused scores
    float a1[8], a2[8];
    #pragma unroll
    for (int i = 0; i < 8; i++) {
        a1[i] = __ldg(a + f0 + i);
        a2[i] = __ldg(a + OUT_F + f0 + i);
    }

    #pragma unroll
    for (int j = 0; j < 2; j++) {
        int gn = nodeBase + n0 + j;
        float hf[8];
        #pragma unroll
        for (int p = 0; p < 4; p++) {
            hf[2 * p]     = __uint_as_float((unsigned)acc[j][p]);
            hf[2 * p + 1] = __uint_as_float((unsigned)(acc[j][p] >> 32));
        }
        if (gn < N_NODES) {
            __half2 o[4];
            #pragma unroll
            for (int p = 0; p < 4; p++)
                o[p] = __floats2half2_rn(hf[2 * p], hf[2 * p + 1]);
            *(float4*)(g_hh + (size_t)gn * OUT_F + f0) = *(float4*)o;
        }
        float s1 = 0.f, s2 = 0.f;
        #pragma unroll
        for (int i = 0; i < 8; i++) {
            s1 = fmaf(hf[i], a1[i], s1);
            s2 = fmaf(hf[i], a2[i], s2);
        }
        #pragma unroll
        for (int o = 1; o < 8; o <<= 1) {
            s1 += __shfl_xor_sync(0xFFFFFFFFu, s1, o);
            s2 += __shfl_xor_sync(0xFFFFFFFFu, s2, o);
        }
        if (tx == 0 && gn < N_NODES) {
            g_s1[gn] = s1;
            g_s2[gn] = s2;
        }
    }
}

// ---------------- build CSR: packed (dst, w), atomic-free ----------------
__global__ __launch_bounds__(256) void k_csr(const int* __restrict__ ei) {
    int e = blockIdx.x * blockDim.x + threadIdx.x;
    if (e >= N_EDGES) return;
    int src = ei[e];
    int dst = ei[N_EDGES + e];
    float s  = __ldg(g_s1 + src) + __ldg(g_s2 + dst);
    float lr = s > 0.f ? s : ALPHA * s;
    float w  = expf(-lr);
    int pos = g_rowstart[src] + g_rank[e];
    g_csr[pos] = (ull)(unsigned)dst | ((ull)__float_as_uint(w) << 32);
}

// ---------------- gather per node (warp), fp16 h, fused divide+ELU ----------------
__global__ __launch_bounds__(256) void k_gather(float* __restrict__ out) {
    int warp = (blockIdx.x * blockDim.x + threadIdx.x) >> 5;
    int lane = threadIdx.x & 31;
    if (warp >= N_NODES) return;

    int s = g_rowstart[warp];
    int e = g_rowstart[warp + 1];

    float ax = 0.f, ay = 0.f, rs = 0.f;
    int i = s;

    #pragma unroll 1
    for (; i + 8 <= e; i += 8) {
        ull v[8];
        #pragma unroll
        for (int j = 0; j < 8; j++) v[j] = g_csr[i + j];
        unsigned hv[8];
        #pragma unroll
        for (int j = 0; j < 8; j++) {
            int d = (int)(unsigned)v[j];
            hv[j] = ((const unsigned*)(g_hh + (size_t)d * OUT_F))[lane];
        }
        #pragma unroll
        for (int j = 0; j < 8; j++) {
            float w = __uint_as_float((unsigned)(v[j] >> 32));
            float2 hf = __half22float2(*(__half2*)&hv[j]);
            rs += w;
            ax = fmaf(w, hf.x, ax);
            ay = fmaf(w, hf.y, ay);
        }
    }
    for (; i < e; i++) {
        ull v = g_csr[i];
        int   d = (int)(unsigned)v;
        float w = __uint_as_float((unsigned)(v >> 32));
        unsigned u = ((const unsigned*)(g_hh + (size_t)d * OUT_F))[lane];
        float2 hf = __half22float2(*(__half2*)&u);
        rs += w;
        ax = fmaf(w, hf.x, ax);
        ay = fmaf(w, hf.y, ay);
    }

    float inv = 1.f / rs;
    float vx = ax * inv;
    float vy = ay * inv;
    vx = vx > 0.f ? vx : expm1f(vx);
    vy = vy > 0.f ? vy : expm1f(vy);
    ((float2*)(out + (size_t)warp * OUT_F))[lane] = make_float2(vx, vy);
}

// ---------------- launch ----------------
extern "C" void kernel_launch(void* const* d_in, const int* in_sizes, int n_in,
                              void* d_out, int out_size) {
    const float* x  = (const float*)d_in[0];
    const float* W  = (const float*)d_in[1];
    const float* a  = (const float*)d_in[2];
    const int*   ei = (const int*)d_in[3];
    float* out = (float*)d_out;

    (void)in_sizes; (void)n_in; (void)out_size;

    // side s2: init -> hist_rank -> scan_a -> scan_c2 (hidden under gemm)
    // main:   gemm (h fp16 + scores) -> [join] csr -> gather
    cudaStream_t s2;
    cudaEvent_t e1, e2;
    cudaStreamCreateWithFlags(&s2, cudaStreamNonBlocking);
    cudaEventCreateWithFlags(&e1, cudaEventDisableTiming);
    cudaEventCreateWithFlags(&e2, cudaEventDisableTiming);

    cudaEventRecord(e1, 0);
    cudaStreamWaitEvent(s2, e1, 0);

    k_init<<<(N_NODES + 255) / 256, 256, 0, s2>>>();
    k_hist_rank<<<(N_EDGES / 4 + 255) / 256, 256, 0, s2>>>(ei);
    k_scan_a<<<SCAN_BLOCKS, 256, 0, s2>>>();

    k_gemm<<<(N_NODES + GB_NODES - 1) / GB_NODES, GB_THREADS>>>(x, W, a);  // 4th launch

    k_scan_c2<<<SCAN_BLOCKS, 256, 0, s2>>>();

    cudaEventRecord(e2, s2);
    cudaStreamWaitEvent(0, e2, 0);

    k_csr<<<(N_EDGES + 255) / 256, 256>>>(ei);
    k_gather<<<(N_NODES * 32 + 255) / 256, 256>>>(out);
}

// round 16
// speedup vs baseline: 1.4752x; 1.4752x over previous
#include <cuda_runtime.h>
#include <cuda_fp16.h>
#include <math.h>

#define N_NODES 50000
#define IN_F    256
#define OUT_F   64
#define N_EDGES 1600000
#define ALPHA   0.2f

#define SCAN_BLOCKS 196   // 196*256 = 50176 >= 50000

#define WSTRIDE 132       // u32 stride per n-row in smem (bank = lane, conflict-free)
#define GEMM_SMEM (2 * 64 * WSTRIDE * 4)   // Whi + Wlo = 67584 B

typedef unsigned long long ull;

// ---------------- scratch (static device globals; no allocation) ----------------
__device__ __align__(16) __half g_hh[(size_t)N_NODES * OUT_F]; // 6.4 MB (fp16 h)
__device__ float g_s1[N_NODES];
__device__ float g_s2[N_NODES];
__device__ int   g_count[N_NODES];
__device__ int   g_rowstart[N_NODES + 1];
__device__ int   g_blocksum[SCAN_BLOCKS];
__device__ __align__(16) int g_rank[N_EDGES];                  // 6.4 MB
__device__ __align__(16) ull g_csr[N_EDGES];                   // 12.8 MB packed (dst, w)
__device__ unsigned g_Whi[64 * 128];                           // W hi, [n][kpair] half2
__device__ unsigned g_Wlo[64 * 128];                           // W lo

// ---------------- zero histogram ----------------
__global__ void k_init() {
    int idx = blockIdx.x * blockDim.x + threadIdx.x;
    if (idx < N_NODES) g_count[idx] = 0;
}

// ---------------- W prep: split fp32 W[k][n] -> hi/lo half2 [n][kpair] ------------
__global__ __launch_bounds__(256) void k_wprep(const float* __restrict__ W) {
    for (int idx = threadIdx.x; idx < 64 * 128; idx += 256) {
        int n  = idx >> 7;
        int kp = idx & 127;
        float v0 = W[(2 * kp) * OUT_F + n];
        float v1 = W[(2 * kp + 1) * OUT_F + n];
        __half h0 = __float2half_rn(v0);
        __half h1 = __float2half_rn(v1);
        __half l0 = __float2half_rn(v0 - __half2float(h0));
        __half l1 = __float2half_rn(v1 - __half2float(h1));
        __half2 hh = __halves2half2(h0, h1);
        __half2 ll = __halves2half2(l0, l1);
        g_Whi[idx] = *(unsigned*)&hh;
        g_Wlo[idx] = *(unsigned*)&ll;
    }
}

// ---------------- histogram of src + per-edge rank ----------------
__global__ __launch_bounds__(256) void k_hist_rank(const int* __restrict__ ei) {
    int t = blockIdx.x * blockDim.x + threadIdx.x;
    if (t >= N_EDGES / 4) return;
    int4 v = ((const int4*)ei)[t];
    int4 r;
    r.x = atomicAdd(&g_count[v.x], 1);
    r.y = atomicAdd(&g_count[v.y], 1);
    r.z = atomicAdd(&g_count[v.z], 1);
    r.w = atomicAdd(&g_count[v.w], 1);
    ((int4*)g_rank)[t] = r;
}

// ---------------- scan stage A: per-block sums ----------------
__global__ __launch_bounds__(256) void k_scan_a() {
    __shared__ int sh[256];
    int i = blockIdx.x * 256 + threadIdx.x;
    sh[threadIdx.x] = (i < N_NODES) ? g_count[i] : 0;
    __syncthreads();
    for (int o = 128; o > 0; o >>= 1) {
        if (threadIdx.x < o) sh[threadIdx.x] += sh[threadIdx.x + o];
        __syncthreads();
    }
    if (threadIdx.x == 0) g_blocksum[blockIdx.x] = sh[0];
}

// ---------------- scan stage C2: self-service global offset + local scan ----------
__global__ __launch_bounds__(256) void k_scan_c2() {
    __shared__ int sh[256];
    __shared__ int s_base;
    int t = threadIdx.x;

    int partial = 0;
    if (t < SCAN_BLOCKS && t < blockIdx.x) partial = g_blocksum[t];
    sh[t] = partial;
    __syncthreads();
    for (int o = 128; o > 0; o >>= 1) {
        if (t < o) sh[t] += sh[t + o];
        __syncthreads();
    }
    if (t == 0) s_base = sh[0];
    __syncthreads();

    int i = blockIdx.x * 256 + t;
    int cnt = (i < N_NODES) ? g_count[i] : 0;
    sh[t] = cnt;
    __syncthreads();
    #pragma unroll
    for (int o = 1; o < 256; o <<= 1) {
        int v = 0;
        if (t >= o) v = sh[t - o];
        __syncthreads();
        sh[t] += v;
        __syncthreads();
    }
    if (i < N_NODES) g_rowstart[i] = s_base + sh[t] - cnt;
    if (blockIdx.x == SCAN_BLOCKS - 1 && t == 0) g_rowstart[N_NODES] = N_EDGES;
}

// ---------------- mma helper ----------------
__device__ __forceinline__ void mma16816(float* c, const unsigned* A,
                                         unsigned b0, unsigned b1) {
    asm volatile(
        "mma.sync.aligned.m16n8k16.row.col.f32.f16.f16.f32 "
        "{%0,%1,%2,%3}, {%4,%5,%6,%7}, {%8,%9}, {%0,%1,%2,%3};"
        : "+f"(c[0]), "+f"(c[1]), "+f"(c[2]), "+f"(c[3])
        : "r"(A[0]), "r"(A[1]), "r"(A[2]), "r"(A[3]), "r"(b0), "r"(b1));
}
__device__ __forceinline__ unsigned split_pack(float a, float b, unsigned& lo) {
    __half h0 = __float2half_rn(a);
    __half h1 = __float2half_rn(b);
    __half l0 = __float2half_rn(a - __half2float(h0));
    __half l1 = __float2half_rn(b - __half2float(h1));
    __half2 hh = __halves2half2(h0, h1);
    __half2 ll = __halves2half2(l0, l1);
    lo = *(unsigned*)&ll;
    return *(unsigned*)&hh;
}

// ---------------- h = x @ W via mma.sync fp16 hi/lo + fused scores ----------------
// block: 128 nodes x 64 f, 8 warps; warp w = rows w*16..w*16+15, all 64 cols.
__global__ __launch_bounds__(256) void k_gemm(const float* __restrict__ x,
                                              const float* __restrict__ a) {
    extern __shared__ unsigned wsm[];
    unsigned* Whi = wsm;
    unsigned* Wlo = wsm + 64 * WSTRIDE;

    const int tid  = threadIdx.x;
    const int wid  = tid >> 5;
    const int lane = tid & 31;
    const int g    = lane >> 2;
    const int t    = lane & 3;
    const int nodeBase = blockIdx.x * 128;

    // stage W hi/lo into smem (stride 128 -> WSTRIDE)
    for (int i = tid; i < 64 * 128; i += 256) {
        int n = i >> 7, kp = i & 127;
        Whi[n * WSTRIDE + kp] = g_Whi[i];
        Wlo[n * WSTRIDE + kp] = g_Wlo[i];
    }
    __syncthreads();

    int r0 = nodeBase + wid * 16 + g;
    int r1 = r0 + 8;
    int r0c = r0 < N_NODES ? r0 : N_NODES - 1;
    int r1c = r1 < N_NODES ? r1 : N_NODES - 1;
    const float* xr0 = x + (size_t)r0c * IN_F;
    const float* xr1 = x + (size_t)r1c * IN_F;

    float acc[8][4];
    #pragma unroll
    for (int tl = 0; tl < 8; tl++)
        #pragma unroll
        for (int q = 0; q < 4; q++) acc[tl][q] = 0.f;

    #pragma unroll 2
    for (int kc = 0; kc < IN_F; kc += 16) {
        float2 p0 = *(const float2*)(xr0 + kc + 2 * t);       // row g, k first half
        float2 p1 = *(const float2*)(xr0 + kc + 8 + 2 * t);   // row g, k second half
        float2 p2 = *(const float2*)(xr1 + kc + 2 * t);       // row g+8, first
        float2 p3 = *(const float2*)(xr1 + kc + 8 + 2 * t);   // row g+8, second
        unsigned ahi[4], alo[4];
        ahi[0] = split_pack(p0.x, p0.y, alo[0]);
        ahi[1] = split_pack(p2.x, p2.y, alo[1]);
        ahi[2] = split_pack(p1.x, p1.y, alo[2]);
        ahi[3] = split_pack(p3.x, p3.y, alo[3]);

        int kph = kc >> 1;
        #pragma unroll
        for (int tl = 0; tl < 8; tl++) {
            const unsigned* bh = &Whi[(tl * 8 + g) * WSTRIDE + kph + t];
            const unsigned* bl = &Wlo[(tl * 8 + g) * WSTRIDE + kph + t];
            unsigned bh0 = bh[0], bh1 = bh[4];
            unsigned bl0 = bl[0], bl1 = bl[4];
            mma16816(acc[tl], ahi, bh0, bh1);
            mma16816(acc[tl], ahi, bl0, bl1);
            mma16816(acc[tl], alo, bh0, bh1);
        }
    }

    // epilogue: fp16 h store + fused scores (from fp32 accumulators)
    float s1a = 0.f, s2a = 0.f, s1b = 0.f, s2b = 0.f;
    #pragma unroll
    for (int tl = 0; tl < 8; tl++) {
        int col = tl * 8 + 2 * t;
        float a1c0 = __ldg(a + col), a1c1 = __ldg(a + col + 1);
        float a2c0 = __ldg(a + OUT_F + col), a2c1 = __ldg(a + OUT_F + col + 1);
        s1a = fmaf(acc[tl][0], a1c0, fmaf(acc[tl][1], a1c1, s1a));
        s2a = fmaf(acc[tl][0], a2c0, fmaf(acc[tl][1], a2c1, s2a));
        s1b = fmaf(acc[tl][2], a1c0, fmaf(acc[tl][3], a1c1, s1b));
        s2b = fmaf(acc[tl][2], a2c0, fmaf(acc[tl][3], a2c1, s2b));
        if (r0 < N_NODES) {
            __half2 hv = __floats2half2_rn(acc[tl][0], acc[tl][1]);
            *(unsigned*)(g_hh + (size_t)r0 * OUT_F + col) = *(unsigned*)&hv;
        }
        if (r1 < N_NODES) {
            __half2 hv = __floats2half2_rn(acc[tl][2], acc[tl][3]);
            *(unsigned*)(g_hh + (size_t)r1 * OUT_F + col) = *(unsigned*)&hv;
        }
    }
    #pragma unroll
    for (int o = 1; o < 4; o <<= 1) {
        s1a += __shfl_xor_sync(0xFFFFFFFFu, s1a, o);
        s2a += __shfl_xor_sync(0xFFFFFFFFu, s2a, o);
        s1b += __shfl_xor_sync(0xFFFFFFFFu, s1b, o);
        s2b += __shfl_xor_sync(0xFFFFFFFFu, s2b, o);
    }
    if (t == 0) {
        if (r0 < N_NODES) { g_s1[r0] = s1a; g_s2[r0] = s2a; }
        if (r1 < N_NODES) { g_s1[r1] = s1b; g_s2[r1] = s2b; }
    }
}

// ---------------- build CSR: packed (dst, w), atomic-free ----------------
__global__ __launch_bounds__(256) void k_csr(const int* __restrict__ ei) {
    int e = blockIdx.x * blockDim.x + threadIdx.x;
    if (e >= N_EDGES) return;
    int src = ei[e];
    int dst = ei[N_EDGES + e];
    float s  = __ldg(g_s1 + src) + __ldg(g_s2 + dst);
    float lr = s > 0.f ? s : ALPHA * s;
    float w  = expf(-lr);
    int pos = g_rowstart[src] + g_rank[e];
    g_csr[pos] = (ull)(unsigned)dst | ((ull)__float_as_uint(w) << 32);
}

// ---------------- gather per node (warp), fp16 h, fused divide+ELU ----------------
__global__ __launch_bounds__(256) void k_gather(float* __restrict__ out) {
    int warp = (blockIdx.x * blockDim.x + threadIdx.x) >> 5;
    int lane = threadIdx.x & 31;
    if (warp >= N_NODES) return;

    int s = g_rowstart[warp];
    int e = g_rowstart[warp + 1];

    float ax = 0.f, ay = 0.f, rs = 0.f;
    int i = s;

    #pragma unroll 1
    for (; i + 8 <= e; i += 8) {
        ull v[8];
        #pragma unroll
        for (int j = 0; j < 8; j++) v[j] = g_csr[i + j];
        unsigned hv[8];
        #pragma unroll
        for (int j = 0; j < 8; j++) {
            int d = (int)(unsigned)v[j];
            hv[j] = ((const unsigned*)(g_hh + (size_t)d * OUT_F))[lane];
        }
        #pragma unroll
        for (int j = 0; j < 8; j++) {
            float w = __uint_as_float((unsigned)(v[j] >> 32));
            float2 hf = __half22float2(*(__half2*)&hv[j]);
            rs += w;
            ax = fmaf(w, hf.x, ax);
            ay = fmaf(w, hf.y, ay);
        }
    }
    for (; i < e; i++) {
        ull v = g_csr[i];
        int   d = (int)(unsigned)v;
        float w = __uint_as_float((unsigned)(v >> 32));
        unsigned u = ((const unsigned*)(g_hh + (size_t)d * OUT_F))[lane];
        float2 hf = __half22float2(*(__half2*)&u);
        rs += w;
        ax = fmaf(w, hf.x, ax);
        ay = fmaf(w, hf.y, ay);
    }

    float inv = 1.f / rs;
    float vx = ax * inv;
    float vy = ay * inv;
    vx = vx > 0.f ? vx : expm1f(vx);
    vy = vy > 0.f ? vy : expm1f(vy);
    ((float2*)(out + (size_t)warp * OUT_F))[lane] = make_float2(vx, vy);
}

// ---------------- launch ----------------
extern "C" void kernel_launch(void* const* d_in, const int* in_sizes, int n_in,
                              void* d_out, int out_size) {
    const float* x  = (const float*)d_in[0];
    const float* W  = (const float*)d_in[1];
    const float* a  = (const float*)d_in[2];
    const int*   ei = (const int*)d_in[3];
    float* out = (float*)d_out;

    (void)in_sizes; (void)n_in; (void)out_size;

    cudaFuncSetAttribute(k_gemm, cudaFuncAttributeMaxDynamicSharedMemorySize,
                         GEMM_SMEM);

    // side s2: init -> hist_rank -> scan_a -> scan_c2 (hidden under gemm)
    // main:   wprep -> gemm (mma, h fp16 + scores) -> [join] csr -> gather
    cudaStream_t s2;
    cudaEvent_t e1, e2;
    cudaStreamCreateWithFlags(&s2, cudaStreamNonBlocking);
    cudaEventCreateWithFlags(&e1, cudaEventDisableTiming);
    cudaEventCreateWithFlags(&e2, cudaEventDisableTiming);

    cudaEventRecord(e1, 0);
    cudaStreamWaitEvent(s2, e1, 0);

    k_wprep<<<1, 256>>>(W);                                      // 1 (main)
    k_init<<<(N_NODES + 255) / 256, 256, 0, s2>>>();             // 2
    k_hist_rank<<<(N_EDGES / 4 + 255) / 256, 256, 0, s2>>>(ei);  // 3
    k_gemm<<<(N_NODES + 127) / 128, 256, GEMM_SMEM>>>(x, a);     // 4 <- ncu

    k_scan_a<<<SCAN_BLOCKS, 256, 0, s2>>>();
    k_scan_c2<<<SCAN_BLOCKS, 256, 0, s2>>>();

    cudaEventRecord(e2, s2);
    cudaStreamWaitEvent(0, e2, 0);

    k_csr<<<(N_EDGES + 255) / 256, 256>>>(ei);
    k_gather<<<(N_NODES * 32 + 255) / 256, 256>>>(out);
}

// round 17
// speedup vs baseline: 1.5570x; 1.0554x over previous
#include <cuda_runtime.h>
#include <cuda_fp16.h>
#include <math.h>

#define N_NODES 50000
#define IN_F    256
#define OUT_F   64
#define N_EDGES 1600000
#define ALPHA   0.2f

#define SCAN_BLOCKS 196   // 196*256 = 50176 >= 50000

#define WSTRIDE 132       // u32 stride per n-row in smem (conflict-free B-frag loads)
#define GEMM_SMEM (2 * 64 * WSTRIDE * 4)   // Whi + Wlo = 67584 B

typedef unsigned long long ull;

// ---------------- scratch (static device globals; no allocation) ----------------
__device__ __align__(16) __half g_hh[(size_t)N_NODES * OUT_F]; // 6.4 MB (fp16 h)
__device__ float g_s1[N_NODES];
__device__ float g_s2[N_NODES];
__device__ int   g_count[N_NODES];
__device__ int   g_rowstart[N_NODES + 1];
__device__ int   g_blocksum[SCAN_BLOCKS];
__device__ __align__(16) int g_rank[N_EDGES];                  // 6.4 MB
__device__ __align__(16) int g_csrd[N_EDGES];                  // 6.4 MB (dst only)

// ---------------- zero histogram ----------------
__global__ void k_init() {
    int idx = blockIdx.x * blockDim.x + threadIdx.x;
    if (idx < N_NODES) g_count[idx] = 0;
}

// ---------------- histogram of src + per-edge rank ----------------
__global__ __launch_bounds__(256) void k_hist_rank(const int* __restrict__ ei) {
    int t = blockIdx.x * blockDim.x + threadIdx.x;
    if (t >= N_EDGES / 4) return;
    int4 v = ((const int4*)ei)[t];
    int4 r;
    r.x = atomicAdd(&g_count[v.x], 1);
    r.y = atomicAdd(&g_count[v.y], 1);
    r.z = atomicAdd(&g_count[v.z], 1);
    r.w = atomicAdd(&g_count[v.w], 1);
    ((int4*)g_rank)[t] = r;
}

// ---------------- scan stage A: per-block sums ----------------
__global__ __launch_bounds__(256) void k_scan_a() {
    __shared__ int sh[256];
    int i = blockIdx.x * 256 + threadIdx.x;
    sh[threadIdx.x] = (i < N_NODES) ? g_count[i] : 0;
    __syncthreads();
    for (int o = 128; o > 0; o >>= 1) {
        if (threadIdx.x < o) sh[threadIdx.x] += sh[threadIdx.x + o];
        __syncthreads();
    }
    if (threadIdx.x == 0) g_blocksum[blockIdx.x] = sh[0];
}

// ---------------- scan stage C2: self-service global offset + local scan ----------
__global__ __launch_bounds__(256) void k_scan_c2() {
    __shared__ int sh[256];
    __shared__ int s_base;
    int t = threadIdx.x;

    int partial = 0;
    if (t < SCAN_BLOCKS && t < blockIdx.x) partial = g_blocksum[t];
    sh[t] = partial;
    __syncthreads();
    for (int o = 128; o > 0; o >>= 1) {
        if (t < o) sh[t] += sh[t + o];
        __syncthreads();
    }
    if (t == 0) s_base = sh[0];
    __syncthreads();

    int i = blockIdx.x * 256 + t;
    int cnt = (i < N_NODES) ? g_count[i] : 0;
    sh[t] = cnt;
    __syncthreads();
    #pragma unroll
    for (int o = 1; o < 256; o <<= 1) {
        int v = 0;
        if (t >= o) v = sh[t - o];
        __syncthreads();
        sh[t] += v;
        __syncthreads();
    }
    if (i < N_NODES) g_rowstart[i] = s_base + sh[t] - cnt;
    if (blockIdx.x == SCAN_BLOCKS - 1 && t == 0) g_rowstart[N_NODES] = N_EDGES;
}

// ---------------- build CSR (dst only, atomic-free; score-free -> side stream) -----
__global__ __launch_bounds__(256) void k_csr_lite(const int* __restrict__ ei) {
    int e = blockIdx.x * blockDim.x + threadIdx.x;
    if (e >= N_EDGES) return;
    int src = ei[e];
    int dst = ei[N_EDGES + e];
    g_csrd[g_rowstart[src] + g_rank[e]] = dst;
}

// ---------------- mma helpers ----------------
__device__ __forceinline__ void mma16816(float* c, const unsigned* A,
                                         unsigned b0, unsigned b1) {
    asm volatile(
        "mma.sync.aligned.m16n8k16.row.col.f32.f16.f16.f32 "
        "{%0,%1,%2,%3}, {%4,%5,%6,%7}, {%8,%9}, {%0,%1,%2,%3};"
        : "+f"(c[0]), "+f"(c[1]), "+f"(c[2]), "+f"(c[3])
        : "r"(A[0]), "r"(A[1]), "r"(A[2]), "r"(A[3]), "r"(b0), "r"(b1));
}
__device__ __forceinline__ unsigned split_pack(float a, float b, unsigned& lo) {
    __half h0 = __float2half_rn(a);
    __half h1 = __float2half_rn(b);
    __half l0 = __float2half_rn(a - __half2float(h0));
    __half l1 = __float2half_rn(b - __half2float(h1));
    __half2 hh = __halves2half2(h0, h1);
    __half2 ll = __halves2half2(l0, l1);
    lo = *(unsigned*)&ll;
    return *(unsigned*)&hh;
}

// ---------------- h = x @ W via mma.sync fp16 hi/lo + fused scores ----------------
// block: 128 nodes x 64 f, 8 warps; W split into hi/lo during staging (wprep fused).
__global__ __launch_bounds__(256) void k_gemm(const float* __restrict__ x,
                                              const float* __restrict__ W,
                                              const float* __restrict__ a) {
    extern __shared__ unsigned wsm[];
    unsigned* Whi = wsm;
    unsigned* Wlo = wsm + 64 * WSTRIDE;

    const int tid  = threadIdx.x;
    const int wid  = tid >> 5;
    const int lane = tid & 31;
    const int g    = lane >> 2;
    const int t    = lane & 3;
    const int nodeBase = blockIdx.x * 128;

    // stage + split W: [k][n] fp32 -> hi/lo half2 [n][kpair] (coalesced reads on n)
    for (int i = tid; i < 64 * 128; i += 256) {
        int kp = i >> 6;
        int n  = i & 63;
        float v0 = __ldg(W + (2 * kp) * OUT_F + n);
        float v1 = __ldg(W + (2 * kp + 1) * OUT_F + n);
        unsigned lo;
        unsigned hi = split_pack(v0, v1, lo);
        Whi[n * WSTRIDE + kp] = hi;
        Wlo[n * WSTRIDE + kp] = lo;
    }
    __syncthreads();

    int r0 = nodeBase + wid * 16 + g;
    int r1 = r0 + 8;
    int r0c = r0 < N_NODES ? r0 : N_NODES - 1;
    int r1c = r1 < N_NODES ? r1 : N_NODES - 1;
    const float* xr0 = x + (size_t)r0c * IN_F;
    const float* xr1 = x + (size_t)r1c * IN_F;

    float acc[8][4];
    #pragma unroll
    for (int tl = 0; tl < 8; tl++)
        #pragma unroll
        for (int q = 0; q < 4; q++) acc[tl][q] = 0.f;

    #pragma unroll 2
    for (int kc = 0; kc < IN_F; kc += 16) {
        float2 p0 = *(const float2*)(xr0 + kc + 2 * t);
        float2 p1 = *(const float2*)(xr0 + kc + 8 + 2 * t);
        float2 p2 = *(const float2*)(xr1 + kc + 2 * t);
        float2 p3 = *(const float2*)(xr1 + kc + 8 + 2 * t);
        unsigned ahi[4], alo[4];
        ahi[0] = split_pack(p0.x, p0.y, alo[0]);
        ahi[1] = split_pack(p2.x, p2.y, alo[1]);
        ahi[2] = split_pack(p1.x, p1.y, alo[2]);
        ahi[3] = split_pack(p3.x, p3.y, alo[3]);

        int kph = kc >> 1;
        #pragma unroll
        for (int tl = 0; tl < 8; tl++) {
            const unsigned* bh = &Whi[(tl * 8 + g) * WSTRIDE + kph + t];
            const unsigned* bl = &Wlo[(tl * 8 + g) * WSTRIDE + kph + t];
            unsigned bh0 = bh[0], bh1 = bh[4];
            unsigned bl0 = bl[0], bl1 = bl[4];
            mma16816(acc[tl], ahi, bh0, bh1);
            mma16816(acc[tl], ahi, bl0, bl1);
            mma16816(acc[tl], alo, bh0, bh1);
        }
    }

    // epilogue: fp16 h store + fused scores (from fp32 accumulators)
    float s1a = 0.f, s2a = 0.f, s1b = 0.f, s2b = 0.f;
    #pragma unroll
    for (int tl = 0; tl < 8; tl++) {
        int col = tl * 8 + 2 * t;
        float a1c0 = __ldg(a + col), a1c1 = __ldg(a + col + 1);
        float a2c0 = __ldg(a + OUT_F + col), a2c1 = __ldg(a + OUT_F + col + 1);
        s1a = fmaf(acc[tl][0], a1c0, fmaf(acc[tl][1], a1c1, s1a));
        s2a = fmaf(acc[tl][0], a2c0, fmaf(acc[tl][1], a2c1, s2a));
        s1b = fmaf(acc[tl][2], a1c0, fmaf(acc[tl][3], a1c1, s1b));
        s2b = fmaf(acc[tl][2], a2c0, fmaf(acc[tl][3], a2c1, s2b));
        if (r0 < N_NODES) {
            __half2 hv = __floats2half2_rn(acc[tl][0], acc[tl][1]);
            *(unsigned*)(g_hh + (size_t)r0 * OUT_F + col) = *(unsigned*)&hv;
        }
        if (r1 < N_NODES) {
            __half2 hv = __floats2half2_rn(acc[tl][2], acc[tl][3]);
            *(unsigned*)(g_hh + (size_t)r1 * OUT_F + col) = *(unsigned*)&hv;
        }
    }
    #pragma unroll
    for (int o = 1; o < 4; o <<= 1) {
        s1a += __shfl_xor_sync(0xFFFFFFFFu, s1a, o);
        s2a += __shfl_xor_sync(0xFFFFFFFFu, s2a, o);
        s1b += __shfl_xor_sync(0xFFFFFFFFu, s1b, o);
        s2b += __shfl_xor_sync(0xFFFFFFFFu, s2b, o);
    }
    if (t == 0) {
        if (r0 < N_NODES) { g_s1[r0] = s1a; g_s2[r0] = s2a; }
        if (r1 < N_NODES) { g_s1[r1] = s1b; g_s2[r1] = s2b; }
    }
}

// ---------------- gather per node (warp): lane-parallel exp + shfl broadcast -------
__global__ __launch_bounds__(256) void k_gather(float* __restrict__ out) {
    int warp = (blockIdx.x * blockDim.x + threadIdx.x) >> 5;
    int lane = threadIdx.x & 31;
    if (warp >= N_NODES) return;

    int s = g_rowstart[warp];
    int e = g_rowstart[warp + 1];
    float s1 = __ldg(g_s1 + warp);

    float ax = 0.f, ay = 0.f, rs = 0.f;
    int i = s;

    // full 32-edge chunks: each lane computes one edge's weight, then broadcast
    for (; i + 32 <= e; i += 32) {
        int   dl = __ldg(g_csrd + i + lane);
        float sc = s1 + __ldg(g_s2 + dl);
        float lr = sc > 0.f ? sc : ALPHA * sc;
        float wl = expf(-lr);
        #pragma unroll 8
        for (int j = 0; j < 32; j++) {
            int   dj = __shfl_sync(0xFFFFFFFFu, dl, j);
            float wj = __shfl_sync(0xFFFFFFFFu, wl, j);
            unsigned u = ((const unsigned*)(g_hh + (size_t)dj * OUT_F))[lane];
            float2 hf = __half22float2(*(__half2*)&u);
            rs += wj;
            ax = fmaf(wj, hf.x, ax);
            ay = fmaf(wj, hf.y, ay);
        }
    }
    // tail (< 32 edges)
    int rem = e - i;
    if (rem > 0) {
        int   dl = 0;
        float wl = 0.f;
        if (lane < rem) {
            dl = __ldg(g_csrd + i + lane);
            float sc = s1 + __ldg(g_s2 + dl);
            float lr = sc > 0.f ? sc : ALPHA * sc;
            wl = expf(-lr);
        }
        for (int j = 0; j < rem; j++) {
            int   dj = __shfl_sync(0xFFFFFFFFu, dl, j);
            float wj = __shfl_sync(0xFFFFFFFFu, wl, j);
            unsigned u = ((const unsigned*)(g_hh + (size_t)dj * OUT_F))[lane];
            float2 hf = __half22float2(*(__half2*)&u);
            rs += wj;
            ax = fmaf(wj, hf.x, ax);
            ay = fmaf(wj, hf.y, ay);
        }
    }

    float inv = 1.f / rs;
    float vx = ax * inv;
    float vy = ay * inv;
    vx = vx > 0.f ? vx : expm1f(vx);
    vy = vy > 0.f ? vy : expm1f(vy);
    ((float2*)(out + (size_t)warp * OUT_F))[lane] = make_float2(vx, vy);
}

// ---------------- launch ----------------
extern "C" void kernel_launch(void* const* d_in, const int* in_sizes, int n_in,
                              void* d_out, int out_size) {
    const float* x  = (const float*)d_in[0];
    const float* W  = (const float*)d_in[1];
    const float* a  = (const float*)d_in[2];
    const int*   ei = (const int*)d_in[3];
    float* out = (float*)d_out;

    (void)in_sizes; (void)n_in; (void)out_size;

    cudaFuncSetAttribute(k_gemm, cudaFuncAttributeMaxDynamicSharedMemorySize,
                         GEMM_SMEM);

    // side s2: init -> hist_rank -> scan_a -> scan_c2 -> csr_lite (all hidden)
    // main:   gemm (mma, W split fused, h fp16 + scores) -> [join] gather
    cudaStream_t s2;
    cudaEvent_t e1, e2;
    cudaStreamCreateWithFlags(&s2, cudaStreamNonBlocking);
    cudaEventCreateWithFlags(&e1, cudaEventDisableTiming);
    cudaEventCreateWithFlags(&e2, cudaEventDisableTiming);

    cudaEventRecord(e1, 0);
    cudaStreamWaitEvent(s2, e1, 0);

    k_init<<<(N_NODES + 255) / 256, 256, 0, s2>>>();              // 1
    k_hist_rank<<<(N_EDGES / 4 + 255) / 256, 256, 0, s2>>>(ei);   // 2
    k_scan_a<<<SCAN_BLOCKS, 256, 0, s2>>>();                      // 3
    k_gemm<<<(N_NODES + 127) / 128, 256, GEMM_SMEM>>>(x, W, a);   // 4 <- ncu

    k_scan_c2<<<SCAN_BLOCKS, 256, 0, s2>>>();
    k_csr_lite<<<(N_EDGES + 255) / 256, 256, 0, s2>>>(ei);

    cudaEventRecord(e2, s2);
    cudaStreamWaitEvent(0, e2, 0);
    k_gather<<<(N_NODES * 32 + 255) / 256, 256>>>(out);
}